// round 16
// baseline (speedup 1.0000x reference)
#include <cuda_runtime.h>
#include <cuda_bf16.h>

#define DEV_INLINE __device__ __forceinline__

// Problem constants
constexpr int cB  = 8;
constexpr int cNW = 1024;
constexpr int cD  = 512;
constexpr int cH  = 8;
constexpr int cL  = 4;
constexpr int cFF = 2048;
constexpr int cK  = 512;
constexpr int cT  = cB * cNW;        // 8192 tokens
constexpr float cSC2   = 0.125f * 1.4426950408889634f;  // SCALE * log2(e)

typedef __nv_bfloat16 bf16;

// ---------------------------------------------------------------------------
// Scratch
// ---------------------------------------------------------------------------
__device__ float g_x   [cT * cD];           // residual (fp32)
__device__ bf16  g_hh  [cT * cD];           // LN out bf16
__device__ bf16  g_qkvh[cT * 3 * cD];       // qkv bf16
__device__ bf16  g_aoh [cT * cD];           // attn out bf16
__device__ bf16  g_ffh [cT * cFF];          // ffn hidden bf16
__device__ bf16  g_wTh [12582912];          // transposed weights bf16

// ---------------------------------------------------------------------------
// Helpers
// ---------------------------------------------------------------------------
DEV_INLINE float gelu_f(float x) {
    float z = 0.7978845608028654f * (x + 0.044715f * x * x * x);
    float t = __expf(2.0f * z);
    float th = 1.0f - 2.0f / (t + 1.0f);
    return 0.5f * x * (1.0f + th);
}

DEV_INLINE unsigned pk2(float lo, float hi) {
    unsigned u;
    asm("cvt.rn.bf16x2.f32 %0, %1, %2;" : "=r"(u) : "f"(hi), "f"(lo));
    return u;
}

DEV_INLINE void mma_bf16(float* d, const unsigned* a, const unsigned* b) {
    asm volatile(
        "mma.sync.aligned.m16n8k16.row.col.f32.bf16.bf16.f32 "
        "{%0,%1,%2,%3}, {%4,%5,%6,%7}, {%8,%9}, {%0,%1,%2,%3};"
        : "+f"(d[0]), "+f"(d[1]), "+f"(d[2]), "+f"(d[3])
        : "r"(a[0]), "r"(a[1]), "r"(a[2]), "r"(a[3]), "r"(b[0]), "r"(b[1]));
}

DEV_INLINE void ldsm4(unsigned* r, unsigned addr) {
    asm volatile("ldmatrix.sync.aligned.m8n8.x4.shared.b16 {%0,%1,%2,%3}, [%4];"
        : "=r"(r[0]), "=r"(r[1]), "=r"(r[2]), "=r"(r[3]) : "r"(addr));
}
DEV_INLINE void ldsm4t(unsigned* r, unsigned addr) {
    asm volatile("ldmatrix.sync.aligned.m8n8.x4.trans.shared.b16 {%0,%1,%2,%3}, [%4];"
        : "=r"(r[0]), "=r"(r[1]), "=r"(r[2]), "=r"(r[3]) : "r"(addr));
}

DEV_INLINE void cp16(unsigned dst, const void* src) {
    asm volatile("cp.async.cg.shared.global [%0], [%1], 16;" :: "r"(dst), "l"(src));
}
#define CP_COMMIT() asm volatile("cp.async.commit_group;" ::: "memory")
#define CP_WAIT1()  asm volatile("cp.async.wait_group 1;" ::: "memory")
#define CP_WAIT0()  asm volatile("cp.async.wait_group 0;" ::: "memory")

// ---------------------------------------------------------------------------
// bf16 tensor-core GEMM, BK=64, 3-stage cp.async + ldmatrix, 2 CTAs/SM.
// ---------------------------------------------------------------------------
template<bool BIAS, bool RES, bool GELU_, bool OBF>
__global__ void __launch_bounds__(256, 2)
k_tgemm(const bf16* __restrict__ A, const bf16* __restrict__ B,
        const float* __restrict__ bias, const float* __restrict__ Res,
        void* __restrict__ Cv, int K, int sA, int sB, int sC)
{
    extern __shared__ __align__(16) unsigned dsm[];
    constexpr int ASZ = 128 * 36;
    constexpr int BSZ = 128 * 36;

    int tid = threadIdx.x;
    int wid = tid >> 5, lane = tid & 31;
    int wm = wid & 1, wn = wid >> 1;
    int lrow = lane & 7, q = lane >> 3;
    int lg = lane >> 2, lt = lane & 3;

    int bm = blockIdx.y * 128, bn = blockIdx.x * 128;
    unsigned smemU = (unsigned)__cvta_generic_to_shared(dsm);

    const int NC = K >> 6;
    float acc[4][4][4] = {};

    int pr = tid >> 3, pf = tid & 7;
    const bf16* Apre = A + (size_t)(bm + pr) * sA + pf * 8;
    const bf16* Bpre = B + (size_t)(bn + pr) * sB + pf * 8;
    unsigned adst = smemU + (pr * 36 + pf * 4) * 4;
    unsigned bdst = smemU + (3 * ASZ + pr * 36 + pf * 4) * 4;

    unsigned aBase = smemU + ((wm * 64 + (q & 1) * 8 + lrow) * 36 + (q >> 1) * 4) * 4;
    unsigned bBase = smemU + (3 * ASZ + (wn * 32 + (q >> 1) * 8 + lrow) * 36 + (q & 1) * 4) * 4;

#define PRE(s, c) do { int k0 = (c) << 6;                                          \
    _Pragma("unroll")                                                              \
    for (int i = 0; i < 4; i++)                                                    \
        cp16(adst + (s) * ASZ * 4 + i * 32 * 36 * 4, Apre + (size_t)i * 32 * sA + k0); \
    _Pragma("unroll")                                                              \
    for (int i = 0; i < 4; i++)                                                    \
        cp16(bdst + (s) * BSZ * 4 + i * 32 * 36 * 4, Bpre + (size_t)i * 32 * sB + k0); \
    CP_COMMIT(); } while (0)

    PRE(0, 0);
    PRE(1, 1);

    for (int c = 0; c < NC; c++) {
        if (c + 1 < NC) CP_WAIT1(); else CP_WAIT0();
        __syncthreads();
        if (c + 2 < NC) PRE((c + 2) % 3, c + 2);

        int st = c % 3;
        unsigned aS = aBase + st * ASZ * 4;
        unsigned bS = bBase + st * BSZ * 4;
        #pragma unroll
        for (int ks = 0; ks < 4; ks++) {
            unsigned af[4][4], bq[2][4];
            #pragma unroll
            for (int ma = 0; ma < 4; ma++) ldsm4(af[ma], aS + (ma * 576 + ks * 8) * 4);
            #pragma unroll
            for (int nb = 0; nb < 2; nb++) ldsm4(bq[nb], bS + (nb * 576 + ks * 8) * 4);
            #pragma unroll
            for (int ma = 0; ma < 4; ma++)
                #pragma unroll
                for (int na = 0; na < 4; na++)
                    mma_bf16(acc[ma][na], af[ma], &bq[na >> 1][(na & 1) * 2]);
        }
    }

    // Epilogue
    #pragma unroll
    for (int ma = 0; ma < 4; ma++) {
        #pragma unroll
        for (int na = 0; na < 4; na++) {
            int row = bm + wm * 64 + ma * 16 + lg;
            int col = bn + wn * 32 + na * 8 + 2 * lt;
            #pragma unroll
            for (int half = 0; half < 2; half++) {
                int r = row + half * 8;
                float v0 = acc[ma][na][half * 2 + 0];
                float v1 = acc[ma][na][half * 2 + 1];
                if (BIAS) { v0 += bias[col]; v1 += bias[col + 1]; }
                if (GELU_) { v0 = gelu_f(v0); v1 = gelu_f(v1); }
                if (RES) {
                    const float* rp = Res + (size_t)r * sC + col;
                    v0 += rp[0]; v1 += rp[1];
                }
                if (OBF) {
                    *(unsigned*)((bf16*)Cv + (size_t)r * sC + col) = pk2(v0, v1);
                } else {
                    *(float2*)((float*)Cv + (size_t)r * sC + col) = make_float2(v0, v1);
                }
            }
        }
    }
#undef PRE
}

// ---------------------------------------------------------------------------
// Flash attention
// ---------------------------------------------------------------------------
__global__ void __launch_bounds__(256, 2)
k_flash(const bf16* __restrict__ qkv, bf16* __restrict__ ao)
{
    extern __shared__ __align__(16) unsigned fsm[];

    int tid = threadIdx.x;
    int wid = tid >> 5, lane = tid & 31;
    int lrow = lane & 7, q = lane >> 3;
    int lg = lane >> 2, lt = lane & 3;
    int bh = blockIdx.y, b = bh >> 3, h = bh & 7;
    int i0 = blockIdx.x * 128;

    unsigned fU = (unsigned)__cvta_generic_to_shared(fsm);

    const bf16* base = qkv + (size_t)b * cNW * 1536;
    const bf16* Qg = base + h * 64;
    const bf16* Kg = base + 512 + h * 64;
    const bf16* Vg = base + 1024 + h * 64;

    #pragma unroll
    for (int i = 0; i < 4; i++) {
        int idx = tid + i * 256;
        int r = idx >> 3, f = idx & 7;
        uint4 v = __ldg((const uint4*)(Qg + (size_t)(i0 + r) * 1536 + f * 8));
        *(uint4*)&fsm[r * 36 + f * 4] = v;
    }

    int pr2 = tid >> 3, pf2 = tid & 7;
    unsigned kdst = fU + (4608 + pr2 * 36 + pf2 * 4) * 4;
    unsigned vdst = fU + (9216 + pr2 * 36 + pf2 * 4) * 4;

#define PREKV(s, jt) do { int j0 = (jt) * 64;                                  \
    cp16(kdst + (s) * 2304 * 4,               Kg + (size_t)(j0 + pr2) * 1536 + pf2 * 8);      \
    cp16(kdst + (s) * 2304 * 4 + 32 * 36 * 4, Kg + (size_t)(j0 + pr2 + 32) * 1536 + pf2 * 8); \
    cp16(vdst + (s) * 2304 * 4,               Vg + (size_t)(j0 + pr2) * 1536 + pf2 * 8);      \
    cp16(vdst + (s) * 2304 * 4 + 32 * 36 * 4, Vg + (size_t)(j0 + pr2 + 32) * 1536 + pf2 * 8); \
    CP_COMMIT(); } while (0)

    PREKV(0, 0);

    unsigned qBase = fU + ((wid * 16 + (q & 1) * 8 + lrow) * 36 + (q >> 1) * 4) * 4;
    unsigned kBase = fU + (4608 + ((q >> 1) * 8 + lrow) * 36 + (q & 1) * 4) * 4;
    unsigned vBase = fU + (9216 + ((q & 1) * 8 + lrow) * 36 + (q >> 1) * 4) * 4;

    __syncthreads();
    unsigned qf[4][4];
    #pragma unroll
    for (int ks = 0; ks < 4; ks++) ldsm4(qf[ks], qBase + ks * 8 * 4);

    float m0 = -1e30f, m1 = -1e30f, l0 = 0.f, l1 = 0.f;
    float o[8][4] = {};
    int qrow = wid * 16 + lg;

    for (int jt = 0; jt < 16; jt++) {
        CP_WAIT0();
        __syncthreads();
        if (jt + 1 < 16) PREKV((jt + 1) & 1, jt + 1);

        int buf = jt & 1;
        unsigned kS = kBase + buf * 2304 * 4;
        unsigned vS = vBase + buf * 2304 * 4;

        float sacc[8][4] = {};
        #pragma unroll
        for (int ks = 0; ks < 4; ks++) {
            #pragma unroll
            for (int nb = 0; nb < 4; nb++) {
                unsigned kq[4];
                ldsm4(kq, kS + (nb * 576 + ks * 8) * 4);
                mma_bf16(sacc[2 * nb],     qf[ks], &kq[0]);
                mma_bf16(sacc[2 * nb + 1], qf[ks], &kq[2]);
            }
        }

        float mx0 = -1e30f, mx1 = -1e30f;
        #pragma unroll
        for (int na = 0; na < 8; na++) {
            #pragma unroll
            for (int c2 = 0; c2 < 4; c2++) sacc[na][c2] *= cSC2;
            mx0 = fmaxf(mx0, fmaxf(sacc[na][0], sacc[na][1]));
            mx1 = fmaxf(mx1, fmaxf(sacc[na][2], sacc[na][3]));
        }
        #pragma unroll
        for (int o2 = 1; o2 < 4; o2 <<= 1) {
            mx0 = fmaxf(mx0, __shfl_xor_sync(0xffffffffu, mx0, o2));
            mx1 = fmaxf(mx1, __shfl_xor_sync(0xffffffffu, mx1, o2));
        }
        float nm0 = fmaxf(m0, mx0), nm1 = fmaxf(m1, mx1);
        float cr0 = exp2f(m0 - nm0), cr1 = exp2f(m1 - nm1);
        m0 = nm0; m1 = nm1;

        float sum0 = 0.f, sum1 = 0.f;
        #pragma unroll
        for (int na = 0; na < 8; na++) {
            sacc[na][0] = exp2f(sacc[na][0] - nm0);
            sacc[na][1] = exp2f(sacc[na][1] - nm0);
            sacc[na][2] = exp2f(sacc[na][2] - nm1);
            sacc[na][3] = exp2f(sacc[na][3] - nm1);
            sum0 += sacc[na][0] + sacc[na][1];
            sum1 += sacc[na][2] + sacc[na][3];
        }
        #pragma unroll
        for (int o2 = 1; o2 < 4; o2 <<= 1) {
            sum0 += __shfl_xor_sync(0xffffffffu, sum0, o2);
            sum1 += __shfl_xor_sync(0xffffffffu, sum1, o2);
        }
        l0 = l0 * cr0 + sum0;
        l1 = l1 * cr1 + sum1;
        #pragma unroll
        for (int na = 0; na < 8; na++) {
            o[na][0] *= cr0; o[na][1] *= cr0;
            o[na][2] *= cr1; o[na][3] *= cr1;
        }

        #pragma unroll
        for (int ks = 0; ks < 4; ks++) {
            unsigned pa[4];
            pa[0] = pk2(sacc[2*ks][0],   sacc[2*ks][1]);
            pa[1] = pk2(sacc[2*ks][2],   sacc[2*ks][3]);
            pa[2] = pk2(sacc[2*ks+1][0], sacc[2*ks+1][1]);
            pa[3] = pk2(sacc[2*ks+1][2], sacc[2*ks+1][3]);
            #pragma unroll
            for (int nb = 0; nb < 4; nb++) {
                unsigned vq[4];
                ldsm4t(vq, vS + (ks * 16 * 36 + nb * 8) * 4);
                mma_bf16(o[2 * nb],     pa, &vq[0]);
                mma_bf16(o[2 * nb + 1], pa, &vq[2]);
            }
        }
    }

    float inv0 = 1.f / l0, inv1 = 1.f / l1;
    bf16* aoG = ao + ((size_t)b * cNW + i0) * cD + h * 64;
    #pragma unroll
    for (int na = 0; na < 8; na++) {
        int col = na * 8 + 2 * lt;
        *(unsigned*)(aoG + (size_t)qrow * cD + col)       = pk2(o[na][0] * inv0, o[na][1] * inv0);
        *(unsigned*)(aoG + (size_t)(qrow + 8) * cD + col) = pk2(o[na][2] * inv1, o[na][3] * inv1);
    }
#undef PREKV
}

// ---------------------------------------------------------------------------
// Merged weight transpose fp32 -> bf16 [N][K]
// ---------------------------------------------------------------------------
__global__ void k_wtall(const float* __restrict__ Wqkv, const float* __restrict__ Wo,
                        const float* __restrict__ W1, const float* __restrict__ W2,
                        bf16* __restrict__ outT) {
    __shared__ float t[32][33];
    int bid = blockIdx.x;
    int layer = bid / 3072;
    int r = bid % 3072;

    const float* in; bf16* out; int R, Cc, tx, ty;
    if (r < 768)        { in = Wqkv + (size_t)layer * 786432;  out = outT + (size_t)layer * 3145728;
                          R = 512; Cc = 1536; tx = r % 48; ty = r / 48; }
    else if (r < 1024)  { r -= 768;
                          in = Wo + (size_t)layer * 262144;    out = outT + (size_t)layer * 3145728 + 786432;
                          R = 512; Cc = 512;  tx = r % 16; ty = r / 16; }
    else if (r < 2048)  { r -= 1024;
                          in = W1 + (size_t)layer * 1048576;   out = outT + (size_t)layer * 3145728 + 1048576;
                          R = 512; Cc = 2048; tx = r % 64; ty = r / 64; }
    else                { r -= 2048;
                          in = W2 + (size_t)layer * 1048576;   out = outT + (size_t)layer * 3145728 + 2097152;
                          R = 2048; Cc = 512; tx = r % 16; ty = r / 16; }

    int c0 = tx * 32, r0 = ty * 32;
    #pragma unroll
    for (int i = 0; i < 4; i++)
        t[threadIdx.y + i * 8][threadIdx.x] = in[(size_t)(r0 + threadIdx.y + i * 8) * Cc + c0 + threadIdx.x];
    __syncthreads();
    #pragma unroll
    for (int i = 0; i < 4; i++)
        out[(size_t)(c0 + threadIdx.y + i * 8) * R + r0 + threadIdx.x] =
            __float2bfloat16(t[threadIdx.x][threadIdx.y + i * 8]);
}

// ---------------------------------------------------------------------------
// Reductions
// ---------------------------------------------------------------------------
template<int NWARPS>
DEV_INLINE void block_sum2(float& s, float& s2) {
    #pragma unroll
    for (int o = 16; o > 0; o >>= 1) {
        s  += __shfl_down_sync(0xffffffffu, s,  o);
        s2 += __shfl_down_sync(0xffffffffu, s2, o);
    }
    __shared__ float sh_a[NWARPS], sh_b[NWARPS];
    int w = threadIdx.x >> 5;
    if ((threadIdx.x & 31) == 0) { sh_a[w] = s; sh_b[w] = s2; }
    __syncthreads();
    if (threadIdx.x == 0) {
        float a = sh_a[0], b = sh_b[0];
        #pragma unroll
        for (int i = 1; i < NWARPS; i++) { a += sh_a[i]; b += sh_b[i]; }
        sh_a[0] = a; sh_b[0] = b;
    }
    __syncthreads();
    s = sh_a[0]; s2 = sh_b[0];
}

// ---------------------------------------------------------------------------
// Embed (unconditional, no flags) + masked-token overwrite
// ---------------------------------------------------------------------------
__global__ void __launch_bounds__(128) k_embed(
    const float* __restrict__ seq, const float* __restrict__ pos_emb,
    const float* __restrict__ p1g, const float* __restrict__ p1b,
    const float* __restrict__ W_emb, const float* __restrict__ b_emb,
    const float* __restrict__ p2g, const float* __restrict__ p2b)
{
    int tok = blockIdx.x;
    int w = tok & (cNW - 1);
    int t = threadIdx.x;
    const float* pos = pos_emb + (size_t)(w + 1) * cD;
    float* out = g_x + (size_t)tok * cD;

    __shared__ float wsm[32];
    __shared__ float lnw[32];
    const float* wrow = seq + (size_t)tok * 32;
    if (t < 32) wsm[t] = wrow[t];
    __syncthreads();
    float m = 0.f;
    #pragma unroll
    for (int c = 0; c < 32; c++) m += wsm[c];
    m *= (1.f / 32.f);
    float v = 0.f;
    #pragma unroll
    for (int c = 0; c < 32; c++) { float d0 = wsm[c] - m; v += d0 * d0; }
    v *= (1.f / 32.f);
    float rs = rsqrtf(v + 1e-5f);
    if (t < 32) lnw[t] = (wsm[t] - m) * rs * p1g[t] + p1b[t];
    __syncthreads();
    float acc[4];
    #pragma unroll
    for (int j = 0; j < 4; j++) {
        int d = t + j * 128;
        float a = b_emb[d];
        #pragma unroll
        for (int c = 0; c < 32; c++) a += lnw[c] * W_emb[c * cD + d];
        acc[j] = a;
    }
    float s = 0.f, s2 = 0.f;
    #pragma unroll
    for (int j = 0; j < 4; j++) { s += acc[j]; s2 += acc[j] * acc[j]; }
    block_sum2<4>(s, s2);
    float mean = s * (1.f / cD);
    float var  = s2 * (1.f / cD) - mean * mean;
    float rstd = rsqrtf(var + 1e-5f);
    #pragma unroll
    for (int j = 0; j < 4; j++) {
        int d = t + j * 128;
        out[d] = (acc[j] - mean) * rstd * p2g[d] + p2b[d] + pos[d];
    }
}

// Overwrite masked token rows with mask_token + pos (runs after k_embed).
__global__ void __launch_bounds__(128) k_masktok(
    const int* __restrict__ mask_idx, const float* __restrict__ pos_emb,
    const float* __restrict__ mtok)
{
    int gi = blockIdx.x;                 // 0 .. B*K-1
    int b = gi / cK;
    int w = mask_idx[gi];
    int t = threadIdx.x;
    const float* pos = pos_emb + (size_t)(w + 1) * cD;
    float* out = g_x + ((size_t)b * cNW + w) * cD;
    #pragma unroll
    for (int j = 0; j < 4; j++) {
        int d = t + j * 128;
        out[d] = mtok[d] + pos[d];
    }
}

// Warp-per-2-rows LayerNorm: 256 threads, 16 rows per block (grid 512).
__global__ void __launch_bounds__(256) k_ln(
    const float* __restrict__ x, const float* __restrict__ g,
    const float* __restrict__ bt, bf16* __restrict__ y)
{
    int warp = threadIdx.x >> 5;
    int lane = threadIdx.x & 31;
    int row0 = blockIdx.x * 16 + warp * 2;
    const float4* xr0 = (const float4*)(x + (size_t)row0 * cD);
    const float4* xr1 = (const float4*)(x + (size_t)(row0 + 1) * cD);
    float4 a0[4], a1[4];
    #pragma unroll
    for (int i = 0; i < 4; i++) a0[i] = xr0[lane + i * 32];
    #pragma unroll
    for (int i = 0; i < 4; i++) a1[i] = xr1[lane + i * 32];

    float s0 = 0.f, q0 = 0.f, s1 = 0.f, q1 = 0.f;
    #pragma unroll
    for (int i = 0; i < 4; i++) {
        s0 += a0[i].x + a0[i].y + a0[i].z + a0[i].w;
        q0 += a0[i].x*a0[i].x + a0[i].y*a0[i].y + a0[i].z*a0[i].z + a0[i].w*a0[i].w;
        s1 += a1[i].x + a1[i].y + a1[i].z + a1[i].w;
        q1 += a1[i].x*a1[i].x + a1[i].y*a1[i].y + a1[i].z*a1[i].z + a1[i].w*a1[i].w;
    }
    #pragma unroll
    for (int o = 16; o > 0; o >>= 1) {
        s0 += __shfl_xor_sync(0xffffffffu, s0, o);
        q0 += __shfl_xor_sync(0xffffffffu, q0, o);
        s1 += __shfl_xor_sync(0xffffffffu, s1, o);
        q1 += __shfl_xor_sync(0xffffffffu, q1, o);
    }
    float mean0 = s0 * (1.f / cD);
    float rstd0 = rsqrtf(q0 * (1.f / cD) - mean0 * mean0 + 1e-5f);
    float mean1 = s1 * (1.f / cD);
    float rstd1 = rsqrtf(q1 * (1.f / cD) - mean1 * mean1 + 1e-5f);

    #pragma unroll
    for (int i = 0; i < 4; i++) {
        int c4 = lane + i * 32;
        float4 gg = ((const float4*)g)[c4];
        float4 bb = ((const float4*)bt)[c4];
        unsigned u0 = pk2((a0[i].x - mean0) * rstd0 * gg.x + bb.x,
                          (a0[i].y - mean0) * rstd0 * gg.y + bb.y);
        unsigned u1 = pk2((a0[i].z - mean0) * rstd0 * gg.z + bb.z,
                          (a0[i].w - mean0) * rstd0 * gg.w + bb.w);
        *(uint2*)(y + (size_t)row0 * cD + c4 * 4) = make_uint2(u0, u1);
        unsigned v0 = pk2((a1[i].x - mean1) * rstd1 * gg.x + bb.x,
                          (a1[i].y - mean1) * rstd1 * gg.y + bb.y);
        unsigned v1 = pk2((a1[i].z - mean1) * rstd1 * gg.z + bb.z,
                          (a1[i].w - mean1) * rstd1 * gg.w + bb.w);
        *(uint2*)(y + (size_t)(row0 + 1) * cD + c4 * 4) = make_uint2(v0, v1);
    }
}

// Output head with FUSED final LayerNorm.
__global__ void __launch_bounds__(256) k_output(
    const float* __restrict__ seq, const int* __restrict__ mask_idx,
    const float* __restrict__ olng, const float* __restrict__ olnb,
    const float* __restrict__ Ww, const float* __restrict__ bw,
    float* __restrict__ out, long long out_size)
{
    int b = blockIdx.y, k = blockIdx.x;
    int idx = mask_idx[b * cK + k];
    const float* xrow = g_x + ((size_t)b * cNW + idx) * cD;
    __shared__ float es[cD];
    __shared__ float lgt[32];
    int t = threadIdx.x;

    float2 v2 = ((const float2*)xrow)[t];
    float s = v2.x + v2.y;
    float s2 = v2.x * v2.x + v2.y * v2.y;
    block_sum2<8>(s, s2);
    float mean = s * (1.f / cD);
    float var  = s2 * (1.f / cD) - mean * mean;
    float rstd = rsqrtf(var + 1e-5f);
    float2 gg = ((const float2*)olng)[t];
    float2 bb = ((const float2*)olnb)[t];
    es[t * 2 + 0] = (v2.x - mean) * rstd * gg.x + bb.x;
    es[t * 2 + 1] = (v2.y - mean) * rstd * gg.y + bb.y;
    __syncthreads();

    int lg = t >> 3, sg = t & 7;
    float part = 0.f;
    #pragma unroll
    for (int c = 0; c < 64; c++) {
        int cc = sg * 64 + c;
        part += es[cc] * Ww[cc * 32 + lg];
    }
    part += __shfl_down_sync(0xffffffffu, part, 4);
    part += __shfl_down_sync(0xffffffffu, part, 2);
    part += __shfl_down_sync(0xffffffffu, part, 1);
    if (sg == 0) lgt[lg] = part + bw[lg];
    __syncthreads();
    size_t base = (size_t)b * cK + k;
    if (t < 8) {
        float l0 = lgt[t*4+0], l1 = lgt[t*4+1], l2 = lgt[t*4+2], l3 = lgt[t*4+3];
        float mx = fmaxf(fmaxf(l0, l1), fmaxf(l2, l3));
        float e0 = expf(l0 - mx), e1 = expf(l1 - mx), e2 = expf(l2 - mx), e3 = expf(l3 - mx);
        float inv = 1.f / (e0 + e1 + e2 + e3);
        size_t off = base * 32 + t * 4;
        if ((long long)(off + 3) < out_size) {
            out[off+0] = e0*inv; out[off+1] = e1*inv; out[off+2] = e2*inv; out[off+3] = e3*inv;
        }
    }
    if (t < 32) {
        size_t off = (size_t)cB * cK * 32 + base * 32 + t;
        if ((long long)off < out_size)
            out[off] = seq[((size_t)b * cNW + idx) * 32 + t];
    }
}

// ---------------------------------------------------------------------------
// Launch
// ---------------------------------------------------------------------------
extern "C" void kernel_launch(void* const* d_in, const int* in_sizes, int n_in,
                              void* d_out, int out_size)
{
    const float* seq      = (const float*)d_in[0];
    const int*   mask_idx = (const int*)  d_in[1];
    const float* pos_emb  = (const float*)d_in[2];
    const float* mtok     = (const float*)d_in[3];
    const float* p1g      = (const float*)d_in[4];
    const float* p1b      = (const float*)d_in[5];
    const float* W_emb    = (const float*)d_in[6];
    const float* b_emb    = (const float*)d_in[7];
    const float* p2g      = (const float*)d_in[8];
    const float* p2b      = (const float*)d_in[9];
    const float* alng     = (const float*)d_in[10];
    const float* alnb     = (const float*)d_in[11];
    const float* Wqkv     = (const float*)d_in[12];
    const float* Wo       = (const float*)d_in[13];
    const float* flng     = (const float*)d_in[14];
    const float* flnb     = (const float*)d_in[15];
    const float* W1       = (const float*)d_in[16];
    const float* b1       = (const float*)d_in[17];
    const float* W2       = (const float*)d_in[18];
    const float* b2       = (const float*)d_in[19];
    const float* olng     = (const float*)d_in[20];
    const float* olnb     = (const float*)d_in[21];
    const float* Ww       = (const float*)d_in[22];
    const float* bw       = (const float*)d_in[23];
    float* out = (float*)d_out;
    (void)in_sizes; (void)n_in;

    float *px;
    bf16 *phh, *pqkvh, *paoh, *pffh, *pwTh;
    cudaGetSymbolAddress((void**)&px,    g_x);
    cudaGetSymbolAddress((void**)&phh,   g_hh);
    cudaGetSymbolAddress((void**)&pqkvh, g_qkvh);
    cudaGetSymbolAddress((void**)&paoh,  g_aoh);
    cudaGetSymbolAddress((void**)&pffh,  g_ffh);
    cudaGetSymbolAddress((void**)&pwTh,  g_wTh);

    const int GSM = 3 * (128 * 36 + 128 * 36) * 4;    // 110592
    const int FSM = (4608 + 2 * 2304 + 2 * 2304) * 4; // 55296
    cudaFuncSetAttribute(k_tgemm<false,false,false,true >, cudaFuncAttributeMaxDynamicSharedMemorySize, GSM);
    cudaFuncSetAttribute(k_tgemm<false,true, false,false>, cudaFuncAttributeMaxDynamicSharedMemorySize, GSM);
    cudaFuncSetAttribute(k_tgemm<true, false,true, true >, cudaFuncAttributeMaxDynamicSharedMemorySize, GSM);
    cudaFuncSetAttribute(k_tgemm<true, true, false,false>, cudaFuncAttributeMaxDynamicSharedMemorySize, GSM);
    cudaFuncSetAttribute(k_flash, cudaFuncAttributeMaxDynamicSharedMemorySize, FSM);

    // embed all tokens, then overwrite masked rows (no flag pass needed)
    k_embed<<<cT, 128>>>(seq, pos_emb, p1g, p1b, W_emb, b_emb, p2g, p2b);
    k_masktok<<<cB * cK, 128>>>(mask_idx, pos_emb, mtok);

    // all weight transposes (fp32 -> bf16 [N][K]) in ONE launch
    k_wtall<<<3072 * cL, dim3(32, 8)>>>(Wqkv, Wo, W1, W2, pwTh);

    for (int l = 0; l < cL; l++) {
        bf16* baseT = pwTh + (size_t)l * 3145728;
        bf16* WqkvT = baseT;
        bf16* WoT   = baseT + 786432;
        bf16* W1T   = baseT + 1048576;
        bf16* W2T   = baseT + 2097152;

        // attention
        k_ln<<<cT / 16, 256>>>(px, alng + l*cD, alnb + l*cD, phh);
        k_tgemm<false,false,false,true><<<dim3(12, 64), 256, GSM>>>(
            phh, WqkvT, nullptr, nullptr, pqkvh, 512, 512, 512, 1536);
        k_flash<<<dim3(8, 64), 256, FSM>>>(pqkvh, paoh);
        k_tgemm<false,true,false,false><<<dim3(4, 64), 256, GSM>>>(
            paoh, WoT, nullptr, px, px, 512, 512, 512, 512);

        // ffn
        k_ln<<<cT / 16, 256>>>(px, flng + l*cD, flnb + l*cD, phh);
        k_tgemm<true,false,true,true><<<dim3(16, 64), 256, GSM>>>(
            phh, W1T, b1 + (size_t)l*cFF, nullptr, pffh, 512, 512, 512, 2048);
        k_tgemm<true,true,false,false><<<dim3(4, 64), 256, GSM>>>(
            pffh, W2T, b2 + (size_t)l*cD, px, px, 2048, 2048, 2048, 512);
    }

    // final LN fused into k_output (only masked rows are ever needed)
    k_output<<<dim3(cK, cB), 256>>>(seq, mask_idx, olng, olnb, Ww, bw, out, (long long)out_size);
}

// round 17
// speedup vs baseline: 1.0081x; 1.0081x over previous
#include <cuda_runtime.h>
#include <cuda_bf16.h>

#define DEV_INLINE __device__ __forceinline__

// Problem constants
constexpr int cB  = 8;
constexpr int cNW = 1024;
constexpr int cD  = 512;
constexpr int cH  = 8;
constexpr int cL  = 4;
constexpr int cFF = 2048;
constexpr int cK  = 512;
constexpr int cT  = cB * cNW;        // 8192 tokens
constexpr float cSC2   = 0.125f * 1.4426950408889634f;  // SCALE * log2(e)

typedef __nv_bfloat16 bf16;

// ---------------------------------------------------------------------------
// Scratch
// ---------------------------------------------------------------------------
__device__ float g_x   [cT * cD];           // residual (fp32)
__device__ bf16  g_hh  [cT * cD];           // LN out bf16
__device__ bf16  g_qkvh[cT * 3 * cD];       // qkv bf16
__device__ bf16  g_aoh [cT * cD];           // attn out bf16
__device__ bf16  g_ffh [cT * cFF];          // ffn hidden bf16
__device__ bf16  g_wTh [12582912];          // transposed weights bf16
__device__ int   g_mflag[cT];

// ---------------------------------------------------------------------------
// Helpers
// ---------------------------------------------------------------------------
DEV_INLINE float gelu_f(float x) {
    float z = 0.7978845608028654f * (x + 0.044715f * x * x * x);
    float t = __expf(2.0f * z);
    float th = 1.0f - 2.0f / (t + 1.0f);
    return 0.5f * x * (1.0f + th);
}

DEV_INLINE unsigned pk2(float lo, float hi) {
    unsigned u;
    asm("cvt.rn.bf16x2.f32 %0, %1, %2;" : "=r"(u) : "f"(hi), "f"(lo));
    return u;
}

DEV_INLINE void mma_bf16(float* d, const unsigned* a, const unsigned* b) {
    asm volatile(
        "mma.sync.aligned.m16n8k16.row.col.f32.bf16.bf16.f32 "
        "{%0,%1,%2,%3}, {%4,%5,%6,%7}, {%8,%9}, {%0,%1,%2,%3};"
        : "+f"(d[0]), "+f"(d[1]), "+f"(d[2]), "+f"(d[3])
        : "r"(a[0]), "r"(a[1]), "r"(a[2]), "r"(a[3]), "r"(b[0]), "r"(b[1]));
}

DEV_INLINE void ldsm4(unsigned* r, unsigned addr) {
    asm volatile("ldmatrix.sync.aligned.m8n8.x4.shared.b16 {%0,%1,%2,%3}, [%4];"
        : "=r"(r[0]), "=r"(r[1]), "=r"(r[2]), "=r"(r[3]) : "r"(addr));
}
DEV_INLINE void ldsm4t(unsigned* r, unsigned addr) {
    asm volatile("ldmatrix.sync.aligned.m8n8.x4.trans.shared.b16 {%0,%1,%2,%3}, [%4];"
        : "=r"(r[0]), "=r"(r[1]), "=r"(r[2]), "=r"(r[3]) : "r"(addr));
}

DEV_INLINE void cp16(unsigned dst, const void* src) {
    asm volatile("cp.async.cg.shared.global [%0], [%1], 16;" :: "r"(dst), "l"(src));
}
#define CP_COMMIT() asm volatile("cp.async.commit_group;" ::: "memory")
#define CP_WAIT1()  asm volatile("cp.async.wait_group 1;" ::: "memory")
#define CP_WAIT0()  asm volatile("cp.async.wait_group 0;" ::: "memory")

// ---------------------------------------------------------------------------
// bf16 tensor-core GEMM, BK=64, 3-stage cp.async + ldmatrix, 2 CTAs/SM.
// ---------------------------------------------------------------------------
template<bool BIAS, bool RES, bool GELU_, bool OBF>
__global__ void __launch_bounds__(256, 2)
k_tgemm(const bf16* __restrict__ A, const bf16* __restrict__ B,
        const float* __restrict__ bias, const float* __restrict__ Res,
        void* __restrict__ Cv, int K, int sA, int sB, int sC)
{
    extern __shared__ __align__(16) unsigned dsm[];
    constexpr int ASZ = 128 * 36;
    constexpr int BSZ = 128 * 36;

    int tid = threadIdx.x;
    int wid = tid >> 5, lane = tid & 31;
    int wm = wid & 1, wn = wid >> 1;
    int lrow = lane & 7, q = lane >> 3;
    int lg = lane >> 2, lt = lane & 3;

    int bm = blockIdx.y * 128, bn = blockIdx.x * 128;
    unsigned smemU = (unsigned)__cvta_generic_to_shared(dsm);

    const int NC = K >> 6;
    float acc[4][4][4] = {};

    int pr = tid >> 3, pf = tid & 7;
    const bf16* Apre = A + (size_t)(bm + pr) * sA + pf * 8;
    const bf16* Bpre = B + (size_t)(bn + pr) * sB + pf * 8;
    unsigned adst = smemU + (pr * 36 + pf * 4) * 4;
    unsigned bdst = smemU + (3 * ASZ + pr * 36 + pf * 4) * 4;

    unsigned aBase = smemU + ((wm * 64 + (q & 1) * 8 + lrow) * 36 + (q >> 1) * 4) * 4;
    unsigned bBase = smemU + (3 * ASZ + (wn * 32 + (q >> 1) * 8 + lrow) * 36 + (q & 1) * 4) * 4;

#define PRE(s, c) do { int k0 = (c) << 6;                                          \
    _Pragma("unroll")                                                              \
    for (int i = 0; i < 4; i++)                                                    \
        cp16(adst + (s) * ASZ * 4 + i * 32 * 36 * 4, Apre + (size_t)i * 32 * sA + k0); \
    _Pragma("unroll")                                                              \
    for (int i = 0; i < 4; i++)                                                    \
        cp16(bdst + (s) * BSZ * 4 + i * 32 * 36 * 4, Bpre + (size_t)i * 32 * sB + k0); \
    CP_COMMIT(); } while (0)

    PRE(0, 0);
    PRE(1, 1);

    for (int c = 0; c < NC; c++) {
        if (c + 1 < NC) CP_WAIT1(); else CP_WAIT0();
        __syncthreads();
        if (c + 2 < NC) PRE((c + 2) % 3, c + 2);

        int st = c % 3;
        unsigned aS = aBase + st * ASZ * 4;
        unsigned bS = bBase + st * BSZ * 4;
        #pragma unroll
        for (int ks = 0; ks < 4; ks++) {
            unsigned af[4][4], bq[2][4];
            #pragma unroll
            for (int ma = 0; ma < 4; ma++) ldsm4(af[ma], aS + (ma * 576 + ks * 8) * 4);
            #pragma unroll
            for (int nb = 0; nb < 2; nb++) ldsm4(bq[nb], bS + (nb * 576 + ks * 8) * 4);
            #pragma unroll
            for (int ma = 0; ma < 4; ma++)
                #pragma unroll
                for (int na = 0; na < 4; na++)
                    mma_bf16(acc[ma][na], af[ma], &bq[na >> 1][(na & 1) * 2]);
        }
    }

    // Epilogue
    #pragma unroll
    for (int ma = 0; ma < 4; ma++) {
        #pragma unroll
        for (int na = 0; na < 4; na++) {
            int row = bm + wm * 64 + ma * 16 + lg;
            int col = bn + wn * 32 + na * 8 + 2 * lt;
            #pragma unroll
            for (int half = 0; half < 2; half++) {
                int r = row + half * 8;
                float v0 = acc[ma][na][half * 2 + 0];
                float v1 = acc[ma][na][half * 2 + 1];
                if (BIAS) { v0 += bias[col]; v1 += bias[col + 1]; }
                if (GELU_) { v0 = gelu_f(v0); v1 = gelu_f(v1); }
                if (RES) {
                    const float* rp = Res + (size_t)r * sC + col;
                    v0 += rp[0]; v1 += rp[1];
                }
                if (OBF) {
                    *(unsigned*)((bf16*)Cv + (size_t)r * sC + col) = pk2(v0, v1);
                } else {
                    *(float2*)((float*)Cv + (size_t)r * sC + col) = make_float2(v0, v1);
                }
            }
        }
    }
#undef PRE
}

// ---------------------------------------------------------------------------
// Flash attention
// ---------------------------------------------------------------------------
__global__ void __launch_bounds__(256, 2)
k_flash(const bf16* __restrict__ qkv, bf16* __restrict__ ao)
{
    extern __shared__ __align__(16) unsigned fsm[];

    int tid = threadIdx.x;
    int wid = tid >> 5, lane = tid & 31;
    int lrow = lane & 7, q = lane >> 3;
    int lg = lane >> 2, lt = lane & 3;
    int bh = blockIdx.y, b = bh >> 3, h = bh & 7;
    int i0 = blockIdx.x * 128;

    unsigned fU = (unsigned)__cvta_generic_to_shared(fsm);

    const bf16* base = qkv + (size_t)b * cNW * 1536;
    const bf16* Qg = base + h * 64;
    const bf16* Kg = base + 512 + h * 64;
    const bf16* Vg = base + 1024 + h * 64;

    #pragma unroll
    for (int i = 0; i < 4; i++) {
        int idx = tid + i * 256;
        int r = idx >> 3, f = idx & 7;
        uint4 v = __ldg((const uint4*)(Qg + (size_t)(i0 + r) * 1536 + f * 8));
        *(uint4*)&fsm[r * 36 + f * 4] = v;
    }

    int pr2 = tid >> 3, pf2 = tid & 7;
    unsigned kdst = fU + (4608 + pr2 * 36 + pf2 * 4) * 4;
    unsigned vdst = fU + (9216 + pr2 * 36 + pf2 * 4) * 4;

#define PREKV(s, jt) do { int j0 = (jt) * 64;                                  \
    cp16(kdst + (s) * 2304 * 4,               Kg + (size_t)(j0 + pr2) * 1536 + pf2 * 8);      \
    cp16(kdst + (s) * 2304 * 4 + 32 * 36 * 4, Kg + (size_t)(j0 + pr2 + 32) * 1536 + pf2 * 8); \
    cp16(vdst + (s) * 2304 * 4,               Vg + (size_t)(j0 + pr2) * 1536 + pf2 * 8);      \
    cp16(vdst + (s) * 2304 * 4 + 32 * 36 * 4, Vg + (size_t)(j0 + pr2 + 32) * 1536 + pf2 * 8); \
    CP_COMMIT(); } while (0)

    PREKV(0, 0);

    unsigned qBase = fU + ((wid * 16 + (q & 1) * 8 + lrow) * 36 + (q >> 1) * 4) * 4;
    unsigned kBase = fU + (4608 + ((q >> 1) * 8 + lrow) * 36 + (q & 1) * 4) * 4;
    unsigned vBase = fU + (9216 + ((q & 1) * 8 + lrow) * 36 + (q >> 1) * 4) * 4;

    __syncthreads();
    unsigned qf[4][4];
    #pragma unroll
    for (int ks = 0; ks < 4; ks++) ldsm4(qf[ks], qBase + ks * 8 * 4);

    float m0 = -1e30f, m1 = -1e30f, l0 = 0.f, l1 = 0.f;
    float o[8][4] = {};
    int qrow = wid * 16 + lg;

    for (int jt = 0; jt < 16; jt++) {
        CP_WAIT0();
        __syncthreads();
        if (jt + 1 < 16) PREKV((jt + 1) & 1, jt + 1);

        int buf = jt & 1;
        unsigned kS = kBase + buf * 2304 * 4;
        unsigned vS = vBase + buf * 2304 * 4;

        float sacc[8][4] = {};
        #pragma unroll
        for (int ks = 0; ks < 4; ks++) {
            #pragma unroll
            for (int nb = 0; nb < 4; nb++) {
                unsigned kq[4];
                ldsm4(kq, kS + (nb * 576 + ks * 8) * 4);
                mma_bf16(sacc[2 * nb],     qf[ks], &kq[0]);
                mma_bf16(sacc[2 * nb + 1], qf[ks], &kq[2]);
            }
        }

        float mx0 = -1e30f, mx1 = -1e30f;
        #pragma unroll
        for (int na = 0; na < 8; na++) {
            #pragma unroll
            for (int c2 = 0; c2 < 4; c2++) sacc[na][c2] *= cSC2;
            mx0 = fmaxf(mx0, fmaxf(sacc[na][0], sacc[na][1]));
            mx1 = fmaxf(mx1, fmaxf(sacc[na][2], sacc[na][3]));
        }
        #pragma unroll
        for (int o2 = 1; o2 < 4; o2 <<= 1) {
            mx0 = fmaxf(mx0, __shfl_xor_sync(0xffffffffu, mx0, o2));
            mx1 = fmaxf(mx1, __shfl_xor_sync(0xffffffffu, mx1, o2));
        }
        float nm0 = fmaxf(m0, mx0), nm1 = fmaxf(m1, mx1);
        float cr0 = exp2f(m0 - nm0), cr1 = exp2f(m1 - nm1);
        m0 = nm0; m1 = nm1;

        float sum0 = 0.f, sum1 = 0.f;
        #pragma unroll
        for (int na = 0; na < 8; na++) {
            sacc[na][0] = exp2f(sacc[na][0] - nm0);
            sacc[na][1] = exp2f(sacc[na][1] - nm0);
            sacc[na][2] = exp2f(sacc[na][2] - nm1);
            sacc[na][3] = exp2f(sacc[na][3] - nm1);
            sum0 += sacc[na][0] + sacc[na][1];
            sum1 += sacc[na][2] + sacc[na][3];
        }
        #pragma unroll
        for (int o2 = 1; o2 < 4; o2 <<= 1) {
            sum0 += __shfl_xor_sync(0xffffffffu, sum0, o2);
            sum1 += __shfl_xor_sync(0xffffffffu, sum1, o2);
        }
        l0 = l0 * cr0 + sum0;
        l1 = l1 * cr1 + sum1;
        #pragma unroll
        for (int na = 0; na < 8; na++) {
            o[na][0] *= cr0; o[na][1] *= cr0;
            o[na][2] *= cr1; o[na][3] *= cr1;
        }

        #pragma unroll
        for (int ks = 0; ks < 4; ks++) {
            unsigned pa[4];
            pa[0] = pk2(sacc[2*ks][0],   sacc[2*ks][1]);
            pa[1] = pk2(sacc[2*ks][2],   sacc[2*ks][3]);
            pa[2] = pk2(sacc[2*ks+1][0], sacc[2*ks+1][1]);
            pa[3] = pk2(sacc[2*ks+1][2], sacc[2*ks+1][3]);
            #pragma unroll
            for (int nb = 0; nb < 4; nb++) {
                unsigned vq[4];
                ldsm4t(vq, vS + (ks * 16 * 36 + nb * 8) * 4);
                mma_bf16(o[2 * nb],     pa, &vq[0]);
                mma_bf16(o[2 * nb + 1], pa, &vq[2]);
            }
        }
    }

    float inv0 = 1.f / l0, inv1 = 1.f / l1;
    bf16* aoG = ao + ((size_t)b * cNW + i0) * cD + h * 64;
    #pragma unroll
    for (int na = 0; na < 8; na++) {
        int col = na * 8 + 2 * lt;
        *(unsigned*)(aoG + (size_t)qrow * cD + col)       = pk2(o[na][0] * inv0, o[na][1] * inv0);
        *(unsigned*)(aoG + (size_t)(qrow + 8) * cD + col) = pk2(o[na][2] * inv1, o[na][3] * inv1);
    }
#undef PREKV
}

// ---------------------------------------------------------------------------
// Merged weight transpose fp32 -> bf16 [N][K]
// ---------------------------------------------------------------------------
__global__ void k_wtall(const float* __restrict__ Wqkv, const float* __restrict__ Wo,
                        const float* __restrict__ W1, const float* __restrict__ W2,
                        bf16* __restrict__ outT) {
    __shared__ float t[32][33];
    int bid = blockIdx.x;
    int layer = bid / 3072;
    int r = bid % 3072;

    const float* in; bf16* out; int R, Cc, tx, ty;
    if (r < 768)        { in = Wqkv + (size_t)layer * 786432;  out = outT + (size_t)layer * 3145728;
                          R = 512; Cc = 1536; tx = r % 48; ty = r / 48; }
    else if (r < 1024)  { r -= 768;
                          in = Wo + (size_t)layer * 262144;    out = outT + (size_t)layer * 3145728 + 786432;
                          R = 512; Cc = 512;  tx = r % 16; ty = r / 16; }
    else if (r < 2048)  { r -= 1024;
                          in = W1 + (size_t)layer * 1048576;   out = outT + (size_t)layer * 3145728 + 1048576;
                          R = 512; Cc = 2048; tx = r % 64; ty = r / 64; }
    else                { r -= 2048;
                          in = W2 + (size_t)layer * 1048576;   out = outT + (size_t)layer * 3145728 + 2097152;
                          R = 2048; Cc = 512; tx = r % 16; ty = r / 16; }

    int c0 = tx * 32, r0 = ty * 32;
    #pragma unroll
    for (int i = 0; i < 4; i++)
        t[threadIdx.y + i * 8][threadIdx.x] = in[(size_t)(r0 + threadIdx.y + i * 8) * Cc + c0 + threadIdx.x];
    __syncthreads();
    #pragma unroll
    for (int i = 0; i < 4; i++)
        out[(size_t)(c0 + threadIdx.y + i * 8) * R + r0 + threadIdx.x] =
            __float2bfloat16(t[threadIdx.x][threadIdx.y + i * 8]);
}

// ---------------------------------------------------------------------------
// Reductions
// ---------------------------------------------------------------------------
template<int NWARPS>
DEV_INLINE void block_sum2(float& s, float& s2) {
    #pragma unroll
    for (int o = 16; o > 0; o >>= 1) {
        s  += __shfl_down_sync(0xffffffffu, s,  o);
        s2 += __shfl_down_sync(0xffffffffu, s2, o);
    }
    __shared__ float sh_a[NWARPS], sh_b[NWARPS];
    int w = threadIdx.x >> 5;
    if ((threadIdx.x & 31) == 0) { sh_a[w] = s; sh_b[w] = s2; }
    __syncthreads();
    if (threadIdx.x == 0) {
        float a = sh_a[0], b = sh_b[0];
        #pragma unroll
        for (int i = 1; i < NWARPS; i++) { a += sh_a[i]; b += sh_b[i]; }
        sh_a[0] = a; sh_b[0] = b;
    }
    __syncthreads();
    s = sh_a[0]; s2 = sh_b[0];
}

// ---------------------------------------------------------------------------
// Flags / embed / ln / output
// ---------------------------------------------------------------------------
__global__ void k_setflags(const int* __restrict__ mask_idx) {
    int i = blockIdx.x * blockDim.x + threadIdx.x;
    if (i < cB * cK) g_mflag[(i / cK) * cNW + mask_idx[i]] = 1;
}

__global__ void __launch_bounds__(128) k_embed(
    const float* __restrict__ seq, const float* __restrict__ pos_emb,
    const float* __restrict__ mtok,
    const float* __restrict__ p1g, const float* __restrict__ p1b,
    const float* __restrict__ W_emb, const float* __restrict__ b_emb,
    const float* __restrict__ p2g, const float* __restrict__ p2b)
{
    int tok = blockIdx.x;
    int flag = __ldg(&g_mflag[tok]);
    int w = tok & (cNW - 1);
    int t = threadIdx.x;
    const float* pos = pos_emb + (size_t)(w + 1) * cD;
    float* out = g_x + (size_t)tok * cD;

    if (flag) {
        #pragma unroll
        for (int j = 0; j < 4; j++) { int d = t + j * 128; out[d] = mtok[d] + pos[d]; }
        return;
    }
    __shared__ float wsm[32];
    __shared__ float lnw[32];
    const float* wrow = seq + (size_t)tok * 32;
    if (t < 32) wsm[t] = wrow[t];
    __syncthreads();
    float m = 0.f;
    #pragma unroll
    for (int c = 0; c < 32; c++) m += wsm[c];
    m *= (1.f / 32.f);
    float v = 0.f;
    #pragma unroll
    for (int c = 0; c < 32; c++) { float d0 = wsm[c] - m; v += d0 * d0; }
    v *= (1.f / 32.f);
    float rs = rsqrtf(v + 1e-5f);
    if (t < 32) lnw[t] = (wsm[t] - m) * rs * p1g[t] + p1b[t];
    __syncthreads();
    float acc[4];
    #pragma unroll
    for (int j = 0; j < 4; j++) {
        int d = t + j * 128;
        float a = b_emb[d];
        #pragma unroll
        for (int c = 0; c < 32; c++) a += lnw[c] * W_emb[c * cD + d];
        acc[j] = a;
    }
    float s = 0.f, s2 = 0.f;
    #pragma unroll
    for (int j = 0; j < 4; j++) { s += acc[j]; s2 += acc[j] * acc[j]; }
    block_sum2<4>(s, s2);
    float mean = s * (1.f / cD);
    float var  = s2 * (1.f / cD) - mean * mean;
    float rstd = rsqrtf(var + 1e-5f);
    #pragma unroll
    for (int j = 0; j < 4; j++) {
        int d = t + j * 128;
        out[d] = (acc[j] - mean) * rstd * p2g[d] + p2b[d] + pos[d];
    }
}

// Warp-per-2-rows LayerNorm: 256 threads, 16 rows per block (grid 512).
// 8 independent LDG.128 per thread front-batched -> MLP 8.
__global__ void __launch_bounds__(256) k_ln(
    const float* __restrict__ x, const float* __restrict__ g,
    const float* __restrict__ bt, bf16* __restrict__ y)
{
    int warp = threadIdx.x >> 5;
    int lane = threadIdx.x & 31;
    int row0 = blockIdx.x * 16 + warp * 2;
    const float4* xr0 = (const float4*)(x + (size_t)row0 * cD);
    const float4* xr1 = (const float4*)(x + (size_t)(row0 + 1) * cD);
    float4 a0[4], a1[4];
    #pragma unroll
    for (int i = 0; i < 4; i++) a0[i] = xr0[lane + i * 32];
    #pragma unroll
    for (int i = 0; i < 4; i++) a1[i] = xr1[lane + i * 32];

    float s0 = 0.f, q0 = 0.f, s1 = 0.f, q1 = 0.f;
    #pragma unroll
    for (int i = 0; i < 4; i++) {
        s0 += a0[i].x + a0[i].y + a0[i].z + a0[i].w;
        q0 += a0[i].x*a0[i].x + a0[i].y*a0[i].y + a0[i].z*a0[i].z + a0[i].w*a0[i].w;
        s1 += a1[i].x + a1[i].y + a1[i].z + a1[i].w;
        q1 += a1[i].x*a1[i].x + a1[i].y*a1[i].y + a1[i].z*a1[i].z + a1[i].w*a1[i].w;
    }
    #pragma unroll
    for (int o = 16; o > 0; o >>= 1) {
        s0 += __shfl_xor_sync(0xffffffffu, s0, o);
        q0 += __shfl_xor_sync(0xffffffffu, q0, o);
        s1 += __shfl_xor_sync(0xffffffffu, s1, o);
        q1 += __shfl_xor_sync(0xffffffffu, q1, o);
    }
    float mean0 = s0 * (1.f / cD);
    float rstd0 = rsqrtf(q0 * (1.f / cD) - mean0 * mean0 + 1e-5f);
    float mean1 = s1 * (1.f / cD);
    float rstd1 = rsqrtf(q1 * (1.f / cD) - mean1 * mean1 + 1e-5f);

    #pragma unroll
    for (int i = 0; i < 4; i++) {
        int c4 = lane + i * 32;
        float4 gg = ((const float4*)g)[c4];
        float4 bb = ((const float4*)bt)[c4];
        unsigned u0 = pk2((a0[i].x - mean0) * rstd0 * gg.x + bb.x,
                          (a0[i].y - mean0) * rstd0 * gg.y + bb.y);
        unsigned u1 = pk2((a0[i].z - mean0) * rstd0 * gg.z + bb.z,
                          (a0[i].w - mean0) * rstd0 * gg.w + bb.w);
        *(uint2*)(y + (size_t)row0 * cD + c4 * 4) = make_uint2(u0, u1);
        unsigned v0 = pk2((a1[i].x - mean1) * rstd1 * gg.x + bb.x,
                          (a1[i].y - mean1) * rstd1 * gg.y + bb.y);
        unsigned v1 = pk2((a1[i].z - mean1) * rstd1 * gg.z + bb.z,
                          (a1[i].w - mean1) * rstd1 * gg.w + bb.w);
        *(uint2*)(y + (size_t)(row0 + 1) * cD + c4 * 4) = make_uint2(v0, v1);
    }
}

// Output head with FUSED final LayerNorm.
__global__ void __launch_bounds__(256) k_output(
    const float* __restrict__ seq, const int* __restrict__ mask_idx,
    const float* __restrict__ olng, const float* __restrict__ olnb,
    const float* __restrict__ Ww, const float* __restrict__ bw,
    float* __restrict__ out, long long out_size)
{
    int b = blockIdx.y, k = blockIdx.x;
    int idx = mask_idx[b * cK + k];
    const float* xrow = g_x + ((size_t)b * cNW + idx) * cD;
    __shared__ float es[cD];
    __shared__ float lgt[32];
    int t = threadIdx.x;

    float2 v2 = ((const float2*)xrow)[t];
    float s = v2.x + v2.y;
    float s2 = v2.x * v2.x + v2.y * v2.y;
    block_sum2<8>(s, s2);
    float mean = s * (1.f / cD);
    float var  = s2 * (1.f / cD) - mean * mean;
    float rstd = rsqrtf(var + 1e-5f);
    float2 gg = ((const float2*)olng)[t];
    float2 bb = ((const float2*)olnb)[t];
    es[t * 2 + 0] = (v2.x - mean) * rstd * gg.x + bb.x;
    es[t * 2 + 1] = (v2.y - mean) * rstd * gg.y + bb.y;
    __syncthreads();

    int lg = t >> 3, sg = t & 7;
    float part = 0.f;
    #pragma unroll
    for (int c = 0; c < 64; c++) {
        int cc = sg * 64 + c;
        part += es[cc] * Ww[cc * 32 + lg];
    }
    part += __shfl_down_sync(0xffffffffu, part, 4);
    part += __shfl_down_sync(0xffffffffu, part, 2);
    part += __shfl_down_sync(0xffffffffu, part, 1);
    if (sg == 0) lgt[lg] = part + bw[lg];
    __syncthreads();
    size_t base = (size_t)b * cK + k;
    if (t < 8) {
        float l0 = lgt[t*4+0], l1 = lgt[t*4+1], l2 = lgt[t*4+2], l3 = lgt[t*4+3];
        float mx = fmaxf(fmaxf(l0, l1), fmaxf(l2, l3));
        float e0 = expf(l0 - mx), e1 = expf(l1 - mx), e2 = expf(l2 - mx), e3 = expf(l3 - mx);
        float inv = 1.f / (e0 + e1 + e2 + e3);
        size_t off = base * 32 + t * 4;
        if ((long long)(off + 3) < out_size) {
            out[off+0] = e0*inv; out[off+1] = e1*inv; out[off+2] = e2*inv; out[off+3] = e3*inv;
        }
    }
    if (t < 32) {
        size_t off = (size_t)cB * cK * 32 + base * 32 + t;
        if ((long long)off < out_size)
            out[off] = seq[((size_t)b * cNW + idx) * 32 + t];
    }
}

// ---------------------------------------------------------------------------
// Launch
// ---------------------------------------------------------------------------
extern "C" void kernel_launch(void* const* d_in, const int* in_sizes, int n_in,
                              void* d_out, int out_size)
{
    const float* seq      = (const float*)d_in[0];
    const int*   mask_idx = (const int*)  d_in[1];
    const float* pos_emb  = (const float*)d_in[2];
    const float* mtok     = (const float*)d_in[3];
    const float* p1g      = (const float*)d_in[4];
    const float* p1b      = (const float*)d_in[5];
    const float* W_emb    = (const float*)d_in[6];
    const float* b_emb    = (const float*)d_in[7];
    const float* p2g      = (const float*)d_in[8];
    const float* p2b      = (const float*)d_in[9];
    const float* alng     = (const float*)d_in[10];
    const float* alnb     = (const float*)d_in[11];
    const float* Wqkv     = (const float*)d_in[12];
    const float* Wo       = (const float*)d_in[13];
    const float* flng     = (const float*)d_in[14];
    const float* flnb     = (const float*)d_in[15];
    const float* W1       = (const float*)d_in[16];
    const float* b1       = (const float*)d_in[17];
    const float* W2       = (const float*)d_in[18];
    const float* b2       = (const float*)d_in[19];
    const float* olng     = (const float*)d_in[20];
    const float* olnb     = (const float*)d_in[21];
    const float* Ww       = (const float*)d_in[22];
    const float* bw       = (const float*)d_in[23];
    float* out = (float*)d_out;
    (void)in_sizes; (void)n_in;

    float *px;
    bf16 *phh, *pqkvh, *paoh, *pffh, *pwTh;
    int  *pflag;
    cudaGetSymbolAddress((void**)&px,    g_x);
    cudaGetSymbolAddress((void**)&phh,   g_hh);
    cudaGetSymbolAddress((void**)&pqkvh, g_qkvh);
    cudaGetSymbolAddress((void**)&paoh,  g_aoh);
    cudaGetSymbolAddress((void**)&pffh,  g_ffh);
    cudaGetSymbolAddress((void**)&pwTh,  g_wTh);
    cudaGetSymbolAddress((void**)&pflag, g_mflag);

    const int GSM = 3 * (128 * 36 + 128 * 36) * 4;    // 110592
    const int FSM = (4608 + 2 * 2304 + 2 * 2304) * 4; // 55296
    cudaFuncSetAttribute(k_tgemm<false,false,false,true >, cudaFuncAttributeMaxDynamicSharedMemorySize, GSM);
    cudaFuncSetAttribute(k_tgemm<false,true, false,false>, cudaFuncAttributeMaxDynamicSharedMemorySize, GSM);
    cudaFuncSetAttribute(k_tgemm<true, false,true, true >, cudaFuncAttributeMaxDynamicSharedMemorySize, GSM);
    cudaFuncSetAttribute(k_tgemm<true, true, false,false>, cudaFuncAttributeMaxDynamicSharedMemorySize, GSM);
    cudaFuncSetAttribute(k_flash, cudaFuncAttributeMaxDynamicSharedMemorySize, FSM);

    cudaMemsetAsync(pflag, 0, cT * sizeof(int));
    k_setflags<<<(cB * cK) / 256, 256>>>(mask_idx);
    k_embed<<<cT, 128>>>(seq, pos_emb, mtok, p1g, p1b, W_emb, b_emb, p2g, p2b);

    // all weight transposes (fp32 -> bf16 [N][K]) in ONE launch
    k_wtall<<<3072 * cL, dim3(32, 8)>>>(Wqkv, Wo, W1, W2, pwTh);

    for (int l = 0; l < cL; l++) {
        bf16* baseT = pwTh + (size_t)l * 3145728;
        bf16* WqkvT = baseT;
        bf16* WoT   = baseT + 786432;
        bf16* W1T   = baseT + 1048576;
        bf16* W2T   = baseT + 2097152;

        // attention
        k_ln<<<cT / 16, 256>>>(px, alng + l*cD, alnb + l*cD, phh);
        k_tgemm<false,false,false,true><<<dim3(12, 64), 256, GSM>>>(
            phh, WqkvT, nullptr, nullptr, pqkvh, 512, 512, 512, 1536);
        k_flash<<<dim3(8, 64), 256, FSM>>>(pqkvh, paoh);
        k_tgemm<false,true,false,false><<<dim3(4, 64), 256, GSM>>>(
            paoh, WoT, nullptr, px, px, 512, 512, 512, 512);

        // ffn
        k_ln<<<cT / 16, 256>>>(px, flng + l*cD, flnb + l*cD, phh);
        k_tgemm<true,false,true,true><<<dim3(16, 64), 256, GSM>>>(
            phh, W1T, b1 + (size_t)l*cFF, nullptr, pffh, 512, 512, 512, 2048);
        k_tgemm<true,true,false,false><<<dim3(4, 64), 256, GSM>>>(
            pffh, W2T, b2 + (size_t)l*cD, px, px, 2048, 2048, 2048, 512);
    }

    // final LN fused into k_output (only masked rows are ever needed)
    k_output<<<dim3(cK, cB), 256>>>(seq, mask_idx, olng, olnb, Ww, bw, out, (long long)out_size);
}